// round 9
// baseline (speedup 1.0000x reference)
#include <cuda_runtime.h>
#include <cuda_fp16.h>
#include <cstdint>

#define L     6400
#define WDIM  80
#define NT    50          // 128-row tiles covering 6400
#define KCH   3           // K' = 3 chunks of 64 fp16 (hh, hl, lh terms)
#define CHUNK_BYTES 16384 // 128 rows * 64 fp16 * 2B
#define STAGE 32768       // A chunk + B chunk per pipeline stage
#define SMEM_DYN (2 * STAGE + 512)

// ---------------- device scratch ----------------
__device__ __half g_Ah[NT * KCH * 128 * 64];   // swizzled fp16 chunks, A side
__device__ __half g_Bh[NT * KCH * 128 * 64];   // swizzled fp16 chunks, B side
__device__ int g_rows[L];
__device__ int g_cols[L];
__device__ int g_counts[2];                    // Mv, Nv (atomic build; reset by final_kernel)
__device__ unsigned long long g_rowmax[L];     // (fkey<<32) | ~orig_j
__device__ unsigned int       g_colmax[L];     // fkey of col max

__device__ __forceinline__ unsigned int fkey(float f) {
    unsigned int u = __float_as_uint(f);
    return (u & 0x80000000u) ? ~u : (u | 0x80000000u);
}
__device__ __forceinline__ unsigned int smem_u32(const void* p) {
    unsigned int a;
    asm("{ .reg .u64 t; cvta.to.shared.u64 t, %1; cvt.u32.u64 %0, t; }" : "=r"(a) : "l"(p));
    return a;
}
__device__ __forceinline__ void ldsm4(unsigned& r0, unsigned& r1, unsigned& r2, unsigned& r3,
                                      unsigned addr) {
    asm volatile("ldmatrix.sync.aligned.m8n8.x4.shared.b16 {%0,%1,%2,%3}, [%4];"
                 : "=r"(r0), "=r"(r1), "=r"(r2), "=r"(r3) : "r"(addr));
}
__device__ __forceinline__ void ldsm2(unsigned& r0, unsigned& r1, unsigned addr) {
    asm volatile("ldmatrix.sync.aligned.m8n8.x2.shared.b16 {%0,%1}, [%2];"
                 : "=r"(r0), "=r"(r1) : "r"(addr));
}
__device__ __forceinline__ void mma16816(float* d, const unsigned* a, const unsigned* b) {
    asm volatile(
        "mma.sync.aligned.m16n8k16.row.col.f32.f16.f16.f32 "
        "{%0,%1,%2,%3},{%4,%5,%6,%7},{%8,%9},{%0,%1,%2,%3};"
        : "+f"(d[0]), "+f"(d[1]), "+f"(d[2]), "+f"(d[3])
        : "r"(a[0]), "r"(a[1]), "r"(a[2]), "r"(a[3]), "r"(b[0]), "r"(b[1]));
}
__device__ __forceinline__ void cp_async16(unsigned saddr, const void* gptr) {
    asm volatile("cp.async.cg.shared.global [%0], [%1], 16;" :: "r"(saddr), "l"(gptr));
}

// ---------------- kernel 1: parallel compaction (order-independent) + zero-init ----------------
__global__ void prep_kernel(const float* __restrict__ sa_vi,
                            const float* __restrict__ sa_ir) {
    int i = blockIdx.x * 256 + threadIdx.x;    // exactly 0..6399
    int lane = threadIdx.x & 31;

    g_rowmax[i] = 0ULL;
    g_colmax[i] = 0u;

    {   // vi rows
        bool v = sa_vi[i] > 0.0f;
        unsigned mask = __ballot_sync(0xffffffffu, v);
        if (mask) {
            int leader = __ffs(mask) - 1;
            int base = 0;
            if (lane == leader) base = atomicAdd(&g_counts[0], __popc(mask));
            base = __shfl_sync(0xffffffffu, base, leader);
            if (v) g_rows[base + __popc(mask & ((1u << lane) - 1u))] = i;
        }
    }
    {   // ir cols
        bool v = sa_ir[i] > 0.0f;
        unsigned mask = __ballot_sync(0xffffffffu, v);
        if (mask) {
            int leader = __ffs(mask) - 1;
            int base = 0;
            if (lane == leader) base = atomicAdd(&g_counts[1], __popc(mask));
            base = __shfl_sync(0xffffffffu, base, leader);
            if (v) g_cols[base + __popc(mask & ((1u << lane) - 1u))] = i;
        }
    }
}

// ---------------- kernel 2: gather + fp16 2-split into swizzled chunks; z=2: upsample ----------------
__device__ __forceinline__ unsigned int pack2h(__half a, __half b) {
    unsigned short ua = __half_as_ushort(a), ub = __half_as_ushort(b);
    return (unsigned int)ua | ((unsigned int)ub << 16);
}

__global__ void gather_kernel(const float* __restrict__ vi,
                              const float* __restrict__ ir,
                              const float* __restrict__ sa_ir,
                              float* __restrict__ out) {
    if (blockIdx.z == 2) {
        // 8x bilinear align_corners upsample, 2 px/thread
        int base = (blockIdx.y * 25 + blockIdx.x) * 256 + threadIdx.x;
#pragma unroll
        for (int h = 0; h < 2; h++) {
            int idx = base + h * 204800;
            int y = idx / 640, x = idx % 640;
            float fy = (float)(y * 79) / 639.0f;
            float fx = (float)(x * 79) / 639.0f;
            int y0 = (int)floorf(fy); if (y0 > 79) y0 = 79;
            int x0 = (int)floorf(fx); if (x0 > 79) x0 = 79;
            int y1 = (y0 + 1 < 80) ? y0 + 1 : 79;
            int x1 = (x0 + 1 < 80) ? x0 + 1 : 79;
            float wy = fy - (float)y0, wx = fx - (float)x0;
            float v00 = sa_ir[y0 * 80 + x0], v10 = sa_ir[y1 * 80 + x0];
            float v01 = sa_ir[y0 * 80 + x1], v11 = sa_ir[y1 * 80 + x1];
            float r0 = v00 * (1.0f - wy) + v10 * wy;
            float r1 = v01 * (1.0f - wy) + v11 * wy;
            out[38400 + idx] = r0 * (1.0f - wx) + r1 * wx;
        }
        return;
    }
    int m  = blockIdx.x * 256 + threadIdx.x;  // 0..6399
    int kc = blockIdx.y * 2;                  // 0..62 even (feature pair)
    bool isA = (blockIdx.z == 0);
    int cnt = isA ? g_counts[0] : g_counts[1];
    const float* src = isA ? vi : ir;
    float s = isA ? 0.15625f : 1.0f;          // fold conf scale (1/6.4) into A
    int sidx = isA ? g_rows[m] : g_cols[m];
    float v0 = 0.0f, v1 = 0.0f;
    if (m < cnt) {
        v0 = src[kc * L + sidx] * s;
        v1 = src[(kc + 1) * L + sidx] * s;
    }
    __half h0 = __float2half_rn(v0);
    __half l0 = __float2half_rn(v0 - __half2float(h0));
    __half h1 = __float2half_rn(v1);
    __half l1 = __float2half_rn(v1 - __half2float(h1));
    // chunk term order — A: h,h,l  B: h,l,h  => hh + hl + lh
    __half c0[KCH], c1[KCH];
    if (isA) { c0[0]=h0; c0[1]=h0; c0[2]=l0; c1[0]=h1; c1[1]=h1; c1[2]=l1; }
    else     { c0[0]=h0; c0[1]=l0; c0[2]=h0; c1[0]=h1; c1[1]=l1; c1[2]=h1; }
    char* basep = isA ? (char*)g_Ah : (char*)g_Bh;
    unsigned off = ((unsigned)(m & 127) << 7) + ((unsigned)kc << 1);
    unsigned sw  = off ^ ((off >> 3) & 0x70);         // SW128: 16B-unit ^= (row&7)
    char* p = basep + (size_t)((m >> 7) * KCH) * CHUNK_BYTES + sw;
#pragma unroll
    for (int c = 0; c < KCH; c++)
        *(unsigned int*)(p + c * CHUNK_BYTES) = pack2h(c0[c], c1[c]);
}

// ---------------- kernel 3: double-buffered HMMA GEMM (K'=192) + fused reductions ----------------
__global__ void __launch_bounds__(256, 2) mma_kernel() {
    int Mv = g_counts[0], Nv = g_counts[1];
    int bm = blockIdx.y, bn = blockIdx.x;
    if (bm * 128 >= Mv || bn * 128 >= Nv) return;

    extern __shared__ __align__(16) char smem[];   // 2 stages x 32K + 512B cols
    int* cols_s = (int*)(smem + 2 * STAGE);
    unsigned long long* rbuf = (unsigned long long*)smem;      // overlay stage0 after compute
    unsigned int*       cbuf = (unsigned int*)(smem + 4096);

    int tid = threadIdx.x, lane = tid & 31, wid = tid >> 5;
    int warp_m = wid >> 2;   // 0..1 -> 64-row half
    int warp_n = wid & 3;    // 0..3 -> 32-col quarter

    if (tid < 128) cols_s[tid] = g_cols[bn * 128 + tid];

    unsigned sbase = smem_u32(smem);
    const char* gA = (const char*)g_Ah + (size_t)bm * KCH * CHUNK_BYTES;
    const char* gB = (const char*)g_Bh + (size_t)bn * KCH * CHUNK_BYTES;

    // prefetch chunk 0 into stage 0
#pragma unroll
    for (int v = 0; v < 4; v++) {
        unsigned off = (unsigned)(v * 256 + tid) * 16;
        cp_async16(sbase + off,         gA + off);
        cp_async16(sbase + 16384 + off, gB + off);
    }
    asm volatile("cp.async.commit_group;" ::: "memory");

    float acc[4][4][4];
#pragma unroll
    for (int i = 0; i < 4; i++)
#pragma unroll
        for (int j = 0; j < 4; j++)
#pragma unroll
            for (int c = 0; c < 4; c++) acc[i][j][c] = 0.0f;

    int mrow = warp_m * 64 + (lane & 7) + ((lane >> 3) & 1) * 8;
    int khA  = lane >> 4;            // x4: lanes 16-31 -> k+8 half
    int nrow = warp_n * 32 + (lane & 7);
    int khB  = (lane >> 3) & 1;      // x2: lanes 8-15 -> k+8 half

#pragma unroll
    for (int ch = 0; ch < KCH; ch++) {
        if (ch + 1 < KCH) {          // prefetch next chunk into the other stage
            unsigned dst = sbase + (unsigned)((ch + 1) & 1) * STAGE;
#pragma unroll
            for (int v = 0; v < 4; v++) {
                unsigned off = (unsigned)(v * 256 + tid) * 16;
                cp_async16(dst + off,         gA + (ch + 1) * CHUNK_BYTES + off);
                cp_async16(dst + 16384 + off, gB + (ch + 1) * CHUNK_BYTES + off);
            }
            asm volatile("cp.async.commit_group;" ::: "memory");
            asm volatile("cp.async.wait_group 1;" ::: "memory");
        } else {
            asm volatile("cp.async.wait_group 0;" ::: "memory");
        }
        __syncthreads();
        unsigned saddrA = sbase + (unsigned)(ch & 1) * STAGE;
        unsigned saddrB = saddrA + 16384;
#pragma unroll
        for (int ks = 0; ks < 4; ks++) {
            unsigned afr[4][4], bfr[4][2];
#pragma unroll
            for (int tm = 0; tm < 4; tm++) {
                int m = mrow + tm * 16;
                unsigned unit = (unsigned)((ks * 2 + khA) ^ (m & 7));
                ldsm4(afr[tm][0], afr[tm][1], afr[tm][2], afr[tm][3],
                      saddrA + (unsigned)m * 128 + unit * 16);
            }
#pragma unroll
            for (int tn = 0; tn < 4; tn++) {
                int n = nrow + tn * 8;
                unsigned unit = (unsigned)((ks * 2 + khB) ^ (n & 7));
                ldsm2(bfr[tn][0], bfr[tn][1],
                      saddrB + (unsigned)n * 128 + unit * 16);
            }
#pragma unroll
            for (int tm = 0; tm < 4; tm++)
#pragma unroll
                for (int tn = 0; tn < 4; tn++)
                    mma16816(acc[tm][tn], afr[tm], bfr[tn]);
        }
        __syncthreads();
    }

    // ---- fused reductions; D fragment: c0,c1 -> row t/4, cols 2(t%4)+{0,1}; c2,c3 -> row+8
    int qrow = lane >> 2;        // 0..7
    int qcol = (lane & 3) * 2;   // 0,2,4,6

#pragma unroll
    for (int tm = 0; tm < 4; tm++) {
#pragma unroll
        for (int h = 0; h < 2; h++) {
            unsigned long long bb = 0ULL;
#pragma unroll
            for (int tn = 0; tn < 4; tn++) {
                int nloc = warp_n * 32 + tn * 8 + qcol;
                unsigned k0 = fkey(acc[tm][tn][h * 2 + 0]);
                unsigned k1 = fkey(acc[tm][tn][h * 2 + 1]);
                unsigned long long p0 = ((unsigned long long)k0 << 32) |
                                        (unsigned int)(~(unsigned int)cols_s[nloc]);
                unsigned long long p1 = ((unsigned long long)k1 << 32) |
                                        (unsigned int)(~(unsigned int)cols_s[nloc + 1]);
                if (p0 > bb) bb = p0;
                if (p1 > bb) bb = p1;
            }
            unsigned long long o1 = __shfl_xor_sync(0xffffffffu, bb, 1);
            if (o1 > bb) bb = o1;
            unsigned long long o2 = __shfl_xor_sync(0xffffffffu, bb, 2);
            if (o2 > bb) bb = o2;
            if ((lane & 3) == 0)
                rbuf[(warp_m * 64 + tm * 16 + qrow + 8 * h) * 4 + warp_n] = bb;
        }
    }
#pragma unroll
    for (int tn = 0; tn < 4; tn++) {
#pragma unroll
        for (int e = 0; e < 2; e++) {
            unsigned bk = 0u;
#pragma unroll
            for (int tm = 0; tm < 4; tm++) {
                unsigned ka = fkey(acc[tm][tn][e]);
                unsigned kb = fkey(acc[tm][tn][2 + e]);
                if (ka > bk) bk = ka;
                if (kb > bk) bk = kb;
            }
            unsigned o;
            o = __shfl_xor_sync(0xffffffffu, bk, 4);  if (o > bk) bk = o;
            o = __shfl_xor_sync(0xffffffffu, bk, 8);  if (o > bk) bk = o;
            o = __shfl_xor_sync(0xffffffffu, bk, 16); if (o > bk) bk = o;
            if (lane < 4)
                cbuf[(warp_n * 32 + tn * 8 + qcol + e) * 2 + warp_m] = bk;
        }
    }
    __syncthreads();

    if (tid < 128) {
        int gm = bm * 128 + tid;
        if (gm < Mv) {
            unsigned long long b0 = rbuf[tid * 4];
#pragma unroll
            for (int w = 1; w < 4; w++) { unsigned long long vv = rbuf[tid * 4 + w]; if (vv > b0) b0 = vv; }
            atomicMax(&g_rowmax[g_rows[gm]], b0);
        }
    } else {
        int c = tid - 128;
        int gn = bn * 128 + c;
        if (gn < Nv) {
            unsigned b0 = cbuf[c * 2];
            unsigned vv = cbuf[c * 2 + 1]; if (vv > b0) b0 = vv;
            atomicMax(&g_colmax[cols_s[c]], b0);
        }
    }
}

// ---------------- kernel 4: finalize matches (+ reset counts for graph replay) ----------------
__global__ void final_kernel(float* __restrict__ out) {
    int i = blockIdx.x * 256 + threadIdx.x;
    if (i == 0) { g_counts[0] = 0; g_counts[1] = 0; }   // next replay's prep starts from 0
    if (i >= L) return;
    out[2 * i]     = (float)((i % WDIM) * 8);
    out[2 * i + 1] = (float)((i / WDIM) * 8);

    unsigned long long p = g_rowmax[i];
    unsigned int key = (unsigned int)(p >> 32);
    int j = 0;
    float mv = 0.0f, sc = 0.0f;
    if (key > 0x80000000u) {                     // conf > 0
        int jj = (int)(~(unsigned int)(p & 0xFFFFFFFFu));
        if (g_colmax[jj] == key) {               // mutual nearest neighbor
            j = jj; mv = 1.0f;
            sc = __uint_as_float(key & 0x7FFFFFFFu);
        }
    }
    out[12800 + 2 * i]     = (float)((j % WDIM) * 8);
    out[12800 + 2 * i + 1] = (float)((j / WDIM) * 8);
    out[25600 + i] = mv;
    out[32000 + i] = sc;
}

// ---------------- launch ----------------
extern "C" void kernel_launch(void* const* d_in, const int* in_sizes, int n_in,
                              void* d_out, int out_size) {
    const float* vi    = (const float*)d_in[0];
    const float* ir    = (const float*)d_in[1];
    const float* sa_vi = (const float*)d_in[2];
    const float* sa_ir = (const float*)d_in[3];
    float* out = (float*)d_out;

    cudaFuncSetAttribute(mma_kernel, cudaFuncAttributeMaxDynamicSharedMemorySize, SMEM_DYN);

    prep_kernel<<<25, 256>>>(sa_vi, sa_ir);
    gather_kernel<<<dim3(25, 32, 3), 256>>>(vi, ir, sa_ir, out);
    mma_kernel<<<dim3(NT, NT), 256, SMEM_DYN>>>();
    final_kernel<<<25, 256>>>(out);
}

// round 11
// speedup vs baseline: 1.5013x; 1.5013x over previous
#include <cuda_runtime.h>
#include <cuda_fp16.h>
#include <cstdint>

#define L     6400
#define WDIM  80
#define NT    50          // 128-row tiles covering 6400
#define KCH   3           // K' = 3 chunks of 64 fp16 (hh, hl, lh terms)
#define CHUNK_BYTES 16384 // 128 rows * 64 fp16 * 2B

// ---------------- device scratch ----------------
__device__ __half g_Ah[NT * KCH * 128 * 64];   // swizzled fp16 chunks, A side
__device__ __half g_Bh[NT * KCH * 128 * 64];   // swizzled fp16 chunks, B side
__device__ int g_rows[L];
__device__ int g_cols[L];
__device__ int g_counts[2];                    // Mv, Nv (atomic build; reset by final_kernel)
__device__ unsigned long long g_rowmax[L];     // (fkey<<32) | ~orig_j
__device__ unsigned int       g_colmax[L];     // fkey of col max

__device__ __forceinline__ unsigned int fkey(float f) {
    unsigned int u = __float_as_uint(f);
    return (u & 0x80000000u) ? ~u : (u | 0x80000000u);
}
__device__ __forceinline__ unsigned int smem_u32(const void* p) {
    unsigned int a;
    asm("{ .reg .u64 t; cvta.to.shared.u64 t, %1; cvt.u32.u64 %0, t; }" : "=r"(a) : "l"(p));
    return a;
}
__device__ __forceinline__ void ldsm4(unsigned& r0, unsigned& r1, unsigned& r2, unsigned& r3,
                                      unsigned addr) {
    asm volatile("ldmatrix.sync.aligned.m8n8.x4.shared.b16 {%0,%1,%2,%3}, [%4];"
                 : "=r"(r0), "=r"(r1), "=r"(r2), "=r"(r3) : "r"(addr));
}
__device__ __forceinline__ void ldsm2(unsigned& r0, unsigned& r1, unsigned addr) {
    asm volatile("ldmatrix.sync.aligned.m8n8.x2.shared.b16 {%0,%1}, [%2];"
                 : "=r"(r0), "=r"(r1) : "r"(addr));
}
__device__ __forceinline__ void mma16816(float* d, const unsigned* a, const unsigned* b) {
    asm volatile(
        "mma.sync.aligned.m16n8k16.row.col.f32.f16.f16.f32 "
        "{%0,%1,%2,%3},{%4,%5,%6,%7},{%8,%9},{%0,%1,%2,%3};"
        : "+f"(d[0]), "+f"(d[1]), "+f"(d[2]), "+f"(d[3])
        : "r"(a[0]), "r"(a[1]), "r"(a[2]), "r"(a[3]), "r"(b[0]), "r"(b[1]));
}

// ---------------- kernel 1: parallel compaction (order-independent) + zero-init ----------------
__global__ void prep_kernel(const float* __restrict__ sa_vi,
                            const float* __restrict__ sa_ir) {
    int i = blockIdx.x * 256 + threadIdx.x;    // exactly 0..6399
    int lane = threadIdx.x & 31;

    g_rowmax[i] = 0ULL;
    g_colmax[i] = 0u;

    {   // vi rows
        bool v = sa_vi[i] > 0.0f;
        unsigned mask = __ballot_sync(0xffffffffu, v);
        if (mask) {
            int leader = __ffs(mask) - 1;
            int base = 0;
            if (lane == leader) base = atomicAdd(&g_counts[0], __popc(mask));
            base = __shfl_sync(0xffffffffu, base, leader);
            if (v) g_rows[base + __popc(mask & ((1u << lane) - 1u))] = i;
        }
    }
    {   // ir cols
        bool v = sa_ir[i] > 0.0f;
        unsigned mask = __ballot_sync(0xffffffffu, v);
        if (mask) {
            int leader = __ffs(mask) - 1;
            int base = 0;
            if (lane == leader) base = atomicAdd(&g_counts[1], __popc(mask));
            base = __shfl_sync(0xffffffffu, base, leader);
            if (v) g_cols[base + __popc(mask & ((1u << lane) - 1u))] = i;
        }
    }
}

// ---------------- kernel 2: gather + fp16 2-split into swizzled chunks; z=2: upsample ----------------
__device__ __forceinline__ unsigned int pack2h(__half a, __half b) {
    unsigned short ua = __half_as_ushort(a), ub = __half_as_ushort(b);
    return (unsigned int)ua | ((unsigned int)ub << 16);
}

__global__ void gather_kernel(const float* __restrict__ vi,
                              const float* __restrict__ ir,
                              const float* __restrict__ sa_ir,
                              float* __restrict__ out) {
    if (blockIdx.z == 2) {
        // 8x bilinear align_corners upsample, 2 px/thread
        int base = (blockIdx.y * 25 + blockIdx.x) * 256 + threadIdx.x;
#pragma unroll
        for (int h = 0; h < 2; h++) {
            int idx = base + h * 204800;
            int y = idx / 640, x = idx % 640;
            float fy = (float)(y * 79) / 639.0f;
            float fx = (float)(x * 79) / 639.0f;
            int y0 = (int)floorf(fy); if (y0 > 79) y0 = 79;
            int x0 = (int)floorf(fx); if (x0 > 79) x0 = 79;
            int y1 = (y0 + 1 < 80) ? y0 + 1 : 79;
            int x1 = (x0 + 1 < 80) ? x0 + 1 : 79;
            float wy = fy - (float)y0, wx = fx - (float)x0;
            float v00 = sa_ir[y0 * 80 + x0], v10 = sa_ir[y1 * 80 + x0];
            float v01 = sa_ir[y0 * 80 + x1], v11 = sa_ir[y1 * 80 + x1];
            float r0 = v00 * (1.0f - wy) + v10 * wy;
            float r1 = v01 * (1.0f - wy) + v11 * wy;
            out[38400 + idx] = r0 * (1.0f - wx) + r1 * wx;
        }
        return;
    }
    int m  = blockIdx.x * 256 + threadIdx.x;  // 0..6399
    int kc = blockIdx.y * 2;                  // 0..62 even (feature pair)
    bool isA = (blockIdx.z == 0);
    int cnt = isA ? g_counts[0] : g_counts[1];
    const float* src = isA ? vi : ir;
    float s = isA ? 0.15625f : 1.0f;          // fold conf scale (1/6.4) into A
    int sidx = isA ? g_rows[m] : g_cols[m];
    float v0 = 0.0f, v1 = 0.0f;
    if (m < cnt) {
        v0 = src[kc * L + sidx] * s;
        v1 = src[(kc + 1) * L + sidx] * s;
    }
    __half h0 = __float2half_rn(v0);
    __half l0 = __float2half_rn(v0 - __half2float(h0));
    __half h1 = __float2half_rn(v1);
    __half l1 = __float2half_rn(v1 - __half2float(h1));
    // chunk term order — A: h,h,l  B: h,l,h  => hh + hl + lh
    __half c0[KCH], c1[KCH];
    if (isA) { c0[0]=h0; c0[1]=h0; c0[2]=l0; c1[0]=h1; c1[1]=h1; c1[2]=l1; }
    else     { c0[0]=h0; c0[1]=l0; c0[2]=h0; c1[0]=h1; c1[1]=l1; c1[2]=h1; }
    char* basep = isA ? (char*)g_Ah : (char*)g_Bh;
    unsigned off = ((unsigned)(m & 127) << 7) + ((unsigned)kc << 1);
    unsigned sw  = off ^ ((off >> 3) & 0x70);         // SW128: 16B-unit ^= (row&7)
    char* p = basep + (size_t)((m >> 7) * KCH) * CHUNK_BYTES + sw;
#pragma unroll
    for (int c = 0; c < KCH; c++)
        *(unsigned int*)(p + c * CHUNK_BYTES) = pack2h(c0[c], c1[c]);
}

// ---------------- kernel 3: HMMA fp16 GEMM (K'=192) + fused max reductions ----------------
__global__ void __launch_bounds__(256, 2) mma_kernel() {
    int Mv = g_counts[0], Nv = g_counts[1];
    int bm = blockIdx.y, bn = blockIdx.x;
    if (bm * 128 >= Mv || bn * 128 >= Nv) return;

    __shared__ __align__(16) char smem[33280];  // [0,16K)=A tile, [16K,32K)=B tile, [32K,+512)=cols
    int* cols_s = (int*)(smem + 32768);
    unsigned long long* rbuf = (unsigned long long*)smem;      // overlay after compute: 128*4 u64
    unsigned int*       cbuf = (unsigned int*)(smem + 4096);   // 128*2 u32

    int tid = threadIdx.x, lane = tid & 31, wid = tid >> 5;
    int warp_m = wid >> 2;   // 0..1 -> 64-row half
    int warp_n = wid & 3;    // 0..3 -> 32-col quarter

    if (tid < 128) cols_s[tid] = g_cols[bn * 128 + tid];

    unsigned sbase = smem_u32(smem);
    unsigned saddrA = sbase, saddrB = sbase + 16384;

    const uint4* gA = (const uint4*)g_Ah + (size_t)bm * KCH * (CHUNK_BYTES / 16);
    const uint4* gB = (const uint4*)g_Bh + (size_t)bn * KCH * (CHUNK_BYTES / 16);
    uint4* sA4 = (uint4*)smem;
    uint4* sB4 = (uint4*)(smem + 16384);

    float acc[4][4][4];
#pragma unroll
    for (int i = 0; i < 4; i++)
#pragma unroll
        for (int j = 0; j < 4; j++)
#pragma unroll
            for (int c = 0; c < 4; c++) acc[i][j][c] = 0.0f;

    for (int ch = 0; ch < KCH; ch++) {
        const uint4* a = gA + ch * (CHUNK_BYTES / 16);
        const uint4* b = gB + ch * (CHUNK_BYTES / 16);
#pragma unroll
        for (int v = 0; v < 4; v++) {
            sA4[v * 256 + tid] = a[v * 256 + tid];
            sB4[v * 256 + tid] = b[v * 256 + tid];
        }
        __syncthreads();
        int mrow = warp_m * 64 + (lane & 7) + ((lane >> 3) & 1) * 8;
        int khA  = lane >> 4;            // x4: lanes 16-31 -> k+8 half
        int nrow = warp_n * 32 + (lane & 7);
        int khB  = (lane >> 3) & 1;      // x2: lanes 8-15 -> k+8 half
#pragma unroll
        for (int ks = 0; ks < 4; ks++) {
            unsigned afr[4][4], bfr[4][2];
#pragma unroll
            for (int tm = 0; tm < 4; tm++) {
                int m = mrow + tm * 16;
                unsigned unit = (unsigned)((ks * 2 + khA) ^ (m & 7));
                ldsm4(afr[tm][0], afr[tm][1], afr[tm][2], afr[tm][3],
                      saddrA + (unsigned)m * 128 + unit * 16);
            }
#pragma unroll
            for (int tn = 0; tn < 4; tn++) {
                int n = nrow + tn * 8;
                unsigned unit = (unsigned)((ks * 2 + khB) ^ (n & 7));
                ldsm2(bfr[tn][0], bfr[tn][1],
                      saddrB + (unsigned)n * 128 + unit * 16);
            }
#pragma unroll
            for (int tm = 0; tm < 4; tm++)
#pragma unroll
                for (int tn = 0; tn < 4; tn++)
                    mma16816(acc[tm][tn], afr[tm], bfr[tn]);
        }
        __syncthreads();
    }

    // ---- fused reductions; D fragment: c0,c1 -> row t/4, cols 2(t%4)+{0,1}; c2,c3 -> row+8
    int qrow = lane >> 2;        // 0..7
    int qcol = (lane & 3) * 2;   // 0,2,4,6

#pragma unroll
    for (int tm = 0; tm < 4; tm++) {
#pragma unroll
        for (int h = 0; h < 2; h++) {
            unsigned long long bb = 0ULL;
#pragma unroll
            for (int tn = 0; tn < 4; tn++) {
                int nloc = warp_n * 32 + tn * 8 + qcol;
                unsigned k0 = fkey(acc[tm][tn][h * 2 + 0]);
                unsigned k1 = fkey(acc[tm][tn][h * 2 + 1]);
                unsigned long long p0 = ((unsigned long long)k0 << 32) |
                                        (unsigned int)(~(unsigned int)cols_s[nloc]);
                unsigned long long p1 = ((unsigned long long)k1 << 32) |
                                        (unsigned int)(~(unsigned int)cols_s[nloc + 1]);
                if (p0 > bb) bb = p0;
                if (p1 > bb) bb = p1;
            }
            unsigned long long o1 = __shfl_xor_sync(0xffffffffu, bb, 1);
            if (o1 > bb) bb = o1;
            unsigned long long o2 = __shfl_xor_sync(0xffffffffu, bb, 2);
            if (o2 > bb) bb = o2;
            if ((lane & 3) == 0)
                rbuf[(warp_m * 64 + tm * 16 + qrow + 8 * h) * 4 + warp_n] = bb;
        }
    }
#pragma unroll
    for (int tn = 0; tn < 4; tn++) {
#pragma unroll
        for (int e = 0; e < 2; e++) {
            unsigned bk = 0u;
#pragma unroll
            for (int tm = 0; tm < 4; tm++) {
                unsigned ka = fkey(acc[tm][tn][e]);
                unsigned kb = fkey(acc[tm][tn][2 + e]);
                if (ka > bk) bk = ka;
                if (kb > bk) bk = kb;
            }
            unsigned o;
            o = __shfl_xor_sync(0xffffffffu, bk, 4);  if (o > bk) bk = o;
            o = __shfl_xor_sync(0xffffffffu, bk, 8);  if (o > bk) bk = o;
            o = __shfl_xor_sync(0xffffffffu, bk, 16); if (o > bk) bk = o;
            if (lane < 4)
                cbuf[(warp_n * 32 + tn * 8 + qcol + e) * 2 + warp_m] = bk;
        }
    }
    __syncthreads();

    if (tid < 128) {
        int gm = bm * 128 + tid;
        if (gm < Mv) {
            unsigned long long b0 = rbuf[tid * 4];
#pragma unroll
            for (int w = 1; w < 4; w++) { unsigned long long vv = rbuf[tid * 4 + w]; if (vv > b0) b0 = vv; }
            atomicMax(&g_rowmax[g_rows[gm]], b0);
        }
    } else {
        int c = tid - 128;
        int gn = bn * 128 + c;
        if (gn < Nv) {
            unsigned b0 = cbuf[c * 2];
            unsigned vv = cbuf[c * 2 + 1]; if (vv > b0) b0 = vv;
            atomicMax(&g_colmax[cols_s[c]], b0);
        }
    }
}

// ---------------- kernel 4: finalize matches (+ reset counts for graph replay) ----------------
__global__ void final_kernel(float* __restrict__ out) {
    int i = blockIdx.x * 256 + threadIdx.x;
    if (i == 0) { g_counts[0] = 0; g_counts[1] = 0; }   // next replay's prep starts from 0
    if (i >= L) return;
    out[2 * i]     = (float)((i % WDIM) * 8);
    out[2 * i + 1] = (float)((i / WDIM) * 8);

    unsigned long long p = g_rowmax[i];
    unsigned int key = (unsigned int)(p >> 32);
    int j = 0;
    float mv = 0.0f, sc = 0.0f;
    if (key > 0x80000000u) {                     // conf > 0
        int jj = (int)(~(unsigned int)(p & 0xFFFFFFFFu));
        if (g_colmax[jj] == key) {               // mutual nearest neighbor
            j = jj; mv = 1.0f;
            sc = __uint_as_float(key & 0x7FFFFFFFu);
        }
    }
    out[12800 + 2 * i]     = (float)((j % WDIM) * 8);
    out[12800 + 2 * i + 1] = (float)((j / WDIM) * 8);
    out[25600 + i] = mv;
    out[32000 + i] = sc;
}

// ---------------- launch ----------------
extern "C" void kernel_launch(void* const* d_in, const int* in_sizes, int n_in,
                              void* d_out, int out_size) {
    const float* vi    = (const float*)d_in[0];
    const float* ir    = (const float*)d_in[1];
    const float* sa_vi = (const float*)d_in[2];
    const float* sa_ir = (const float*)d_in[3];
    float* out = (float*)d_out;

    prep_kernel<<<25, 256>>>(sa_vi, sa_ir);
    gather_kernel<<<dim3(25, 32, 3), 256>>>(vi, ir, sa_ir, out);
    mma_kernel<<<dim3(NT, NT), 256>>>();
    final_kernel<<<25, 256>>>(out);
}